// round 3
// baseline (speedup 1.0000x reference)
#include <cuda_runtime.h>
#include <cuda_bf16.h>

// SpanIndexEncoder: out[t] = sum over nodes n (n < num_nodes, start_n <= t <= end_n) of emb[n]
// Difference array + hierarchical prefix scan along tokens:
//   1. zero d_out (diff array) and g_chunk (per-chunk sums)
//   2. scatter: red.v4 {+emb at start, -emb at end+1} into BOTH diff and g_chunk[chunk]
//   3. warp-per-feature exclusive scan of the 512 chunk sums
//   4. apply: per-chunk inclusive scan (float4-wide, batched loads), seeded by chunk prefix

#define MAX_TOKENS 8192
#define MAX_NODES  8192
#define FEAT       256
#define CHUNK      16
#define CHUNK_SH   4
#define NCHUNK     (MAX_TOKENS / CHUNK)   // 512

__device__ float g_chunk[NCHUNK * FEAT];  // per-chunk sums -> exclusive prefixes (512 KB, L2-resident)

__device__ __forceinline__ void red_add_v4(float* p, float a, float b, float c, float d) {
    asm volatile("red.global.add.v4.f32 [%0], {%1,%2,%3,%4};"
                 :: "l"(p), "f"(a), "f"(b), "f"(c), "f"(d) : "memory");
}

// One node per 64 threads (64 x float4 = 256 features). 4 nodes per 256-thread block.
__global__ void __launch_bounds__(256) scatter_kernel(
    const float* __restrict__ emb,
    const int*   __restrict__ starts,
    const int*   __restrict__ ends,
    const int*   __restrict__ num_nodes_p,
    float*       __restrict__ out)
{
    const int num_nodes = num_nodes_p[0];
    const int n = blockIdx.x * 4 + (threadIdx.x >> 6);
    const int j = (threadIdx.x & 63) << 2;   // feature offset (float4 granularity)
    if (n >= num_nodes) return;
    const int s = starts[n];
    const int e = ends[n];
    if (s > e) return;                        // empty span contributes nothing

    const float4 v = *reinterpret_cast<const float4*>(emb + (size_t)n * FEAT + j);
    red_add_v4(out + (size_t)s * FEAT + j, v.x, v.y, v.z, v.w);
    red_add_v4(&g_chunk[(s >> CHUNK_SH) * FEAT + j], v.x, v.y, v.z, v.w);
    if (e + 1 < MAX_TOKENS) {
        red_add_v4(out + (size_t)(e + 1) * FEAT + j, -v.x, -v.y, -v.z, -v.w);
        red_add_v4(&g_chunk[((e + 1) >> CHUNK_SH) * FEAT + j], -v.x, -v.y, -v.z, -v.w);
    }
}

// One warp per feature (256 blocks x 32 threads): exclusive scan of NCHUNK=512 chunk sums.
// Lane l owns 16 contiguous chunks [16l, 16l+16). All loads are consumed before any store.
__global__ void __launch_bounds__(32) chunk_scan_kernel()
{
    const int f = blockIdx.x;
    const int l = threadIdx.x;
    const int base = l * 16;

    float v[16];
#pragma unroll
    for (int i = 0; i < 16; ++i) v[i] = g_chunk[(base + i) * FEAT + f];
    // local inclusive scan
#pragma unroll
    for (int i = 1; i < 16; ++i) v[i] += v[i - 1];

    // warp inclusive scan of lane totals -> exclusive offset for this lane
    float own = v[15];
    float incl = own;
#pragma unroll
    for (int d = 1; d < 32; d <<= 1) {
        float t = __shfl_up_sync(0xffffffffu, incl, d);
        if (l >= d) incl += t;
    }
    const float excl = incl - own;

    g_chunk[(base + 0) * FEAT + f] = excl;
#pragma unroll
    for (int i = 1; i < 16; ++i)
        g_chunk[(base + i) * FEAT + f] = excl + v[i - 1];
}

// 2 chunks per 128-thread block (64 float4-columns per chunk). Grid = 256 blocks.
// Batch all 16 float4 loads (max MLP), then the short 16-step v4 add chain + stores.
__global__ void __launch_bounds__(128) chunk_apply_kernel(float* __restrict__ out)
{
    const int c = blockIdx.x * 2 + threadIdx.y;
    const int j = threadIdx.x << 2;

    float4 run = *reinterpret_cast<const float4*>(&g_chunk[c * FEAT + j]);
    float* p = out + (size_t)c * CHUNK * FEAT + j;

    float4 v[CHUNK];
#pragma unroll
    for (int t = 0; t < CHUNK; ++t)
        v[t] = *reinterpret_cast<const float4*>(p + (size_t)t * FEAT);

#pragma unroll
    for (int t = 0; t < CHUNK; ++t) {
        run.x += v[t].x; run.y += v[t].y; run.z += v[t].z; run.w += v[t].w;
        *reinterpret_cast<float4*>(p + (size_t)t * FEAT) = run;
    }
}

extern "C" void kernel_launch(void* const* d_in, const int* in_sizes, int n_in,
                              void* d_out, int out_size)
{
    const float* emb    = (const float*)d_in[0];
    const int*   starts = (const int*)d_in[1];
    const int*   ends   = (const int*)d_in[2];
    const int*   nnp    = (const int*)d_in[3];
    float*       out    = (float*)d_out;

    void* gp = nullptr;
    cudaGetSymbolAddress(&gp, g_chunk);

    cudaMemsetAsync(out, 0, (size_t)MAX_TOKENS * FEAT * sizeof(float), 0);
    cudaMemsetAsync(gp, 0, (size_t)NCHUNK * FEAT * sizeof(float), 0);

    scatter_kernel<<<MAX_NODES / 4, 256>>>(emb, starts, ends, nnp, out);
    chunk_scan_kernel<<<FEAT, 32>>>();
    chunk_apply_kernel<<<NCHUNK / 2, dim3(64, 2)>>>(out);
}